// round 1
// baseline (speedup 1.0000x reference)
#include <cuda_runtime.h>
#include <math.h>

#define T_LEN 1024
#define H_DIM 2048
#define NHEAD 32
#define HSZ   64

static const size_t TH = (size_t)T_LEN * H_DIM;   // 2,097,152

// Scratch layout (units: floats). 20 big [T,H] buffers + small MLP temps.
#define OFS_XN   (0*2097152ull)
#define OFS_XR   (1*2097152ull)
#define OFS_XW   (2*2097152ull)
#define OFS_XK   (3*2097152ull)
#define OFS_XV   (4*2097152ull)
#define OFS_XA   (5*2097152ull)
#define OFS_XG   (6*2097152ull)
#define OFS_R    (7*2097152ull)
#define OFS_K    (8*2097152ull)
#define OFS_V    (9*2097152ull)
#define OFS_G    (10*2097152ull)
#define OFS_A    (11*2097152ull)
#define OFS_WD   (12*2097152ull)
#define OFS_VM   (13*2097152ull)
#define OFS_KF   (14*2097152ull)
#define OFS_VF   (15*2097152ull)
#define OFS_AS   (16*2097152ull)
#define OFS_BS   (17*2097152ull)
#define OFS_Y    (18*2097152ull)
#define OFS_OP   (19*2097152ull)
#define OFS_GT   (20*2097152ull)                   // [T,128]
#define OFS_AT   (OFS_GT + 1024ull*128)            // [T,64]
#define OFS_WT   (OFS_AT + 1024ull*64)             // [T,64]
#define OFS_VT   (OFS_WT + 1024ull*64)             // [T,32]
#define SCRATCH_FLOATS (OFS_VT + 1024ull*32)

__device__ float d_scratch[SCRATCH_FLOATS];

// ---------------------------------------------------------------------------
// Generic guarded SGEMM: C[M,N] = epilogue( A[M,K] * (transB ? B[N,K]^T : B[K,N]) )
// modes: 0 none, 1 sigmoid, 2 tanh, 3 sigmoid(bias+v), 4 exp(-0.606531*sigmoid(bias+v)),
//        5 v + X[m,n] (residual add)
// ---------------------------------------------------------------------------
__global__ void gemm_kernel(const float* __restrict__ A, const float* __restrict__ B,
                            float* __restrict__ C, int M, int N, int K,
                            int transB, int mode,
                            const float* __restrict__ bias,
                            const float* __restrict__ X)
{
    __shared__ float As[16][68];
    __shared__ float Bs[16][68];
    const int tid = threadIdx.x;            // 256 threads
    const int tx = tid & 15, ty = tid >> 4;
    const int bm = blockIdx.y * 64, bn = blockIdx.x * 64;
    float acc[4][4] = {};
    for (int k0 = 0; k0 < K; k0 += 16) {
        {
            int r = tid >> 2;
            int c = (tid & 3) << 2;
            int gr = bm + r;
            #pragma unroll
            for (int u = 0; u < 4; u++) {
                int gc = k0 + c + u;
                As[c + u][r] = (gr < M && gc < K) ? A[(size_t)gr * K + gc] : 0.f;
            }
        }
        if (transB) {
            int r = tid >> 2;
            int c = (tid & 3) << 2;
            int gn = bn + r;
            #pragma unroll
            for (int u = 0; u < 4; u++) {
                int gk = k0 + c + u;
                Bs[c + u][r] = (gn < N && gk < K) ? B[(size_t)gn * K + gk] : 0.f;
            }
        } else {
            int kr = tid >> 4;
            int nc = (tid & 15) << 2;
            int gk = k0 + kr;
            #pragma unroll
            for (int u = 0; u < 4; u++) {
                int gn = bn + nc + u;
                Bs[kr][nc + u] = (gk < K && gn < N) ? B[(size_t)gk * N + gn] : 0.f;
            }
        }
        __syncthreads();
        #pragma unroll
        for (int kk = 0; kk < 16; kk++) {
            const float4 a4 = *(const float4*)&As[kk][ty << 2];
            const float4 b4 = *(const float4*)&Bs[kk][tx << 2];
            float a[4] = {a4.x, a4.y, a4.z, a4.w};
            float b[4] = {b4.x, b4.y, b4.z, b4.w};
            #pragma unroll
            for (int i = 0; i < 4; i++)
                #pragma unroll
                for (int j = 0; j < 4; j++)
                    acc[i][j] = fmaf(a[i], b[j], acc[i][j]);
        }
        __syncthreads();
    }
    #pragma unroll
    for (int i = 0; i < 4; i++) {
        int m = bm + (ty << 2) + i;
        if (m >= M) continue;
        #pragma unroll
        for (int j = 0; j < 4; j++) {
            int n = bn + (tx << 2) + j;
            if (n >= N) continue;
            float v = acc[i][j];
            if (mode == 1)      v = 1.f / (1.f + expf(-v));
            else if (mode == 2) v = tanhf(v);
            else if (mode == 3) v = 1.f / (1.f + expf(-(bias[n] + v)));
            else if (mode == 4) v = expf(-0.606531f / (1.f + expf(-(bias[n] + v))));
            else if (mode == 5) v = v + X[(size_t)m * N + n];
            C[(size_t)m * N + n] = v;
        }
    }
}

// ---------------------------------------------------------------------------
// LayerNorm over H=2048 per token (block of 256 threads per token).
// Also writes state1_out (= xn of last token) if s1out != nullptr.
// ---------------------------------------------------------------------------
__global__ void ln1_kernel(const float* __restrict__ x, const float* __restrict__ w,
                           const float* __restrict__ b, float* __restrict__ xn,
                           float* __restrict__ s1out)
{
    __shared__ float sred[8];
    const int t = blockIdx.x;
    const int tid = threadIdx.x;
    const float* xr = x + (size_t)t * H_DIM;
    float v[8];
    float s = 0.f;
    #pragma unroll
    for (int j = 0; j < 8; j++) { v[j] = xr[tid + j * 256]; s += v[j]; }
    #pragma unroll
    for (int o = 16; o > 0; o >>= 1) s += __shfl_xor_sync(0xffffffffu, s, o);
    if ((tid & 31) == 0) sred[tid >> 5] = s;
    __syncthreads();
    float tot = 0.f;
    #pragma unroll
    for (int i = 0; i < 8; i++) tot += sred[i];
    const float mu = tot * (1.f / H_DIM);
    __syncthreads();
    float ss = 0.f;
    #pragma unroll
    for (int j = 0; j < 8; j++) { float d = v[j] - mu; ss += d * d; }
    #pragma unroll
    for (int o = 16; o > 0; o >>= 1) ss += __shfl_xor_sync(0xffffffffu, ss, o);
    if ((tid & 31) == 0) sred[tid >> 5] = ss;
    __syncthreads();
    tot = 0.f;
    #pragma unroll
    for (int i = 0; i < 8; i++) tot += sred[i];
    const float inv = rsqrtf(tot * (1.f / H_DIM) + 1e-5f);
    float* xo = xn + (size_t)t * H_DIM;
    #pragma unroll
    for (int j = 0; j < 8; j++) {
        int h = tid + j * 256;
        float val = (v[j] - mu) * inv * w[h] + b[h];
        xo[h] = val;
        if (s1out != nullptr && t == T_LEN - 1) s1out[h] = val;
    }
}

// ---------------------------------------------------------------------------
// Token-shift mixing: six mixed activation streams.
// ---------------------------------------------------------------------------
__global__ void mix_kernel(const float* __restrict__ xn, const float* __restrict__ s1,
                           const float* __restrict__ cr, const float* __restrict__ cw,
                           const float* __restrict__ ck, const float* __restrict__ cv,
                           const float* __restrict__ ca, const float* __restrict__ cg,
                           float* __restrict__ oxr, float* __restrict__ oxw,
                           float* __restrict__ oxk, float* __restrict__ oxv,
                           float* __restrict__ oxa, float* __restrict__ oxg)
{
    size_t idx = (size_t)blockIdx.x * blockDim.x + threadIdx.x;
    int t = (int)(idx >> 11);
    int h = (int)(idx & 2047);
    float cur = xn[idx];
    float prev = t ? xn[idx - H_DIM] : s1[h];
    float sx = prev - cur;
    oxr[idx] = cur + cr[h] * sx;
    oxw[idx] = cur + cw[h] * sx;
    oxk[idx] = cur + ck[h] * sx;
    oxv[idx] = cur + cv[h] * sx;
    oxa[idx] = cur + ca[h] * sx;
    oxg[idx] = cur + cg[h] * sx;
}

// ---------------------------------------------------------------------------
// 64-thread block sum (2 warps)
// ---------------------------------------------------------------------------
__device__ __forceinline__ float blockSum64(float v)
{
    __shared__ float sred[2];
    #pragma unroll
    for (int o = 16; o > 0; o >>= 1) v += __shfl_xor_sync(0xffffffffu, v, o);
    if ((threadIdx.x & 31) == 0) sred[threadIdx.x >> 5] = v;
    __syncthreads();
    float r = sred[0] + sred[1];
    __syncthreads();
    return r;
}

// ---------------------------------------------------------------------------
// Per-(t,head) preprocessing: kk normalization, k/v modification, a/b seqs.
// ---------------------------------------------------------------------------
__global__ void prep_kernel(const float* __restrict__ kbuf, const float* __restrict__ abuf,
                            const float* __restrict__ vbuf, const float* __restrict__ vmix,
                            const float* __restrict__ v_first,
                            const float* __restrict__ k_k, const float* __restrict__ k_a,
                            float* __restrict__ kf, float* __restrict__ vf,
                            float* __restrict__ a_s, float* __restrict__ b_s)
{
    int t = blockIdx.x >> 5;
    int h = blockIdx.x & 31;
    int i = threadIdx.x;
    int g = h * HSZ + i;
    size_t idx = (size_t)t * H_DIM + g;
    float kv = kbuf[idx];
    float kkv = kv * k_k[g];
    float ss = blockSum64(kkv * kkv);
    float kkn = kkv / (sqrtf(ss) + 1e-12f);
    float av = abuf[idx];
    kf[idx] = kv * (1.f + (av - 1.f) * k_a[g]);
    float vv = vbuf[idx];
    vf[idx] = vv + (v_first[idx] - vv) * vmix[idx];
    b_s[idx] = kkn * av;
    a_s[idx] = -kkn;
}

// ---------------------------------------------------------------------------
// Sequential WKV7 scan. One block per head, 128 threads (2 threads per state row,
// 32 columns each). State rows are independent recurrences.
// ---------------------------------------------------------------------------
__global__ void scan_kernel(const float* __restrict__ rb, const float* __restrict__ wd,
                            const float* __restrict__ kf, const float* __restrict__ a_s,
                            const float* __restrict__ b_s, const float* __restrict__ vf,
                            const float* __restrict__ s2in, float* __restrict__ ybuf,
                            float* __restrict__ s2out)
{
    const int h = blockIdx.x;
    const int tid = threadIdx.x;           // 0..127
    const int row = tid >> 1;
    const int col0 = (tid & 1) << 5;       // 0 or 32
    __shared__ __align__(16) float sh[384];   // [r | w | k | a | b | v] x 64
    float S[32];
    {
        const float* p = s2in + (size_t)h * HSZ * HSZ + (size_t)row * HSZ + col0;
        #pragma unroll
        for (int j = 0; j < 32; j++) S[j] = p[j];
    }
    for (int t = 0; t < T_LEN; t++) {
        const size_t base = (size_t)t * H_DIM + (size_t)h * HSZ;
        sh[tid]       = (tid < 64) ? rb[base + tid]  : wd[base + tid - 64];
        sh[128 + tid] = (tid < 64) ? kf[base + tid]  : a_s[base + tid - 64];
        sh[256 + tid] = (tid < 64) ? b_s[base + tid] : vf[base + tid - 64];
        __syncthreads();
        float sa0 = 0.f, sa1 = 0.f;
        #pragma unroll
        for (int q = 0; q < 8; q++) {
            const float4 w4 = *(const float4*)&sh[64 + col0 + q * 4];
            const float4 a4 = *(const float4*)&sh[192 + col0 + q * 4];
            S[q*4+0] *= w4.x; S[q*4+1] *= w4.y; S[q*4+2] *= w4.z; S[q*4+3] *= w4.w;
            sa0 = fmaf(a4.x, S[q*4+0], sa0);
            sa1 = fmaf(a4.y, S[q*4+1], sa1);
            sa0 = fmaf(a4.z, S[q*4+2], sa0);
            sa1 = fmaf(a4.w, S[q*4+3], sa1);
        }
        float sa = sa0 + sa1;
        sa += __shfl_xor_sync(0xffffffffu, sa, 1);
        const float vi = sh[320 + row];
        float y0 = 0.f, y1 = 0.f;
        #pragma unroll
        for (int q = 0; q < 8; q++) {
            const float4 k4 = *(const float4*)&sh[128 + col0 + q * 4];
            const float4 b4 = *(const float4*)&sh[256 + col0 + q * 4];
            const float4 r4 = *(const float4*)&sh[0   + col0 + q * 4];
            S[q*4+0] = fmaf(sa, b4.x, fmaf(vi, k4.x, S[q*4+0])); y0 = fmaf(S[q*4+0], r4.x, y0);
            S[q*4+1] = fmaf(sa, b4.y, fmaf(vi, k4.y, S[q*4+1])); y1 = fmaf(S[q*4+1], r4.y, y1);
            S[q*4+2] = fmaf(sa, b4.z, fmaf(vi, k4.z, S[q*4+2])); y0 = fmaf(S[q*4+2], r4.z, y0);
            S[q*4+3] = fmaf(sa, b4.w, fmaf(vi, k4.w, S[q*4+3])); y1 = fmaf(S[q*4+3], r4.w, y1);
        }
        float y = y0 + y1;
        y += __shfl_xor_sync(0xffffffffu, y, 1);
        if ((tid & 1) == 0) ybuf[base + row] = y;
        __syncthreads();
    }
    if (s2out != nullptr) {
        float* p = s2out + (size_t)h * HSZ * HSZ + (size_t)row * HSZ + col0;
        #pragma unroll
        for (int j = 0; j < 32; j++) p[j] = S[j];
    }
}

// ---------------------------------------------------------------------------
// Per-(t,head) GroupNorm(eps=6.4e-4) + ln_x affine + bonus + gate.
// ---------------------------------------------------------------------------
__global__ void post_kernel(const float* __restrict__ ybuf, const float* __restrict__ rb,
                            const float* __restrict__ kf, const float* __restrict__ vf,
                            const float* __restrict__ gb, const float* __restrict__ r_k,
                            const float* __restrict__ lnw, const float* __restrict__ lnb,
                            float* __restrict__ opre)
{
    int t = blockIdx.x >> 5;
    int h = blockIdx.x & 31;
    int i = threadIdx.x;
    int g = h * HSZ + i;
    size_t idx = (size_t)t * H_DIM + g;
    float y = ybuf[idx];
    float mu = blockSum64(y) * (1.f / 64.f);
    float d = y - mu;
    float var = blockSum64(d * d) * (1.f / 64.f);
    float yn = d * rsqrtf(var + 0.00064f);
    float yv = yn * lnw[g] + lnb[g];
    float bon = blockSum64(rb[idx] * kf[idx] * r_k[g]);
    opre[idx] = (yv + bon * vf[idx]) * gb[idx];
}

__global__ void copy_kernel(const float* __restrict__ src, float* __restrict__ dst, size_t n)
{
    size_t i = (size_t)blockIdx.x * blockDim.x + threadIdx.x;
    if (i < n) dst[i] = src[i];
}

// ---------------------------------------------------------------------------
extern "C" void kernel_launch(void* const* d_in, const int* in_sizes, int n_in,
                              void* d_out, int out_size)
{
    const float* x       = (const float*)d_in[0];
    const float* state1  = (const float*)d_in[1];
    const float* state2  = (const float*)d_in[2];
    const float* v_first = (const float*)d_in[3];
    const float* x_r     = (const float*)d_in[4];
    const float* x_w     = (const float*)d_in[5];
    const float* x_k     = (const float*)d_in[6];
    const float* x_v     = (const float*)d_in[7];
    const float* x_a     = (const float*)d_in[8];
    const float* x_g     = (const float*)d_in[9];
    const float* W_r     = (const float*)d_in[10];
    const float* W_k     = (const float*)d_in[11];
    const float* W_v     = (const float*)d_in[12];
    const float* W_o     = (const float*)d_in[13];
    const float* w0      = (const float*)d_in[14];
    const float* w1      = (const float*)d_in[15];
    const float* w2      = (const float*)d_in[16];
    const float* a0      = (const float*)d_in[17];
    const float* a1      = (const float*)d_in[18];
    const float* a2      = (const float*)d_in[19];
    const float* v0      = (const float*)d_in[20];
    const float* v1      = (const float*)d_in[21];
    const float* v2      = (const float*)d_in[22];
    const float* g1      = (const float*)d_in[23];
    const float* g2      = (const float*)d_in[24];
    const float* k_k     = (const float*)d_in[25];
    const float* k_a     = (const float*)d_in[26];
    const float* r_k     = (const float*)d_in[27];
    const float* ln_x_w  = (const float*)d_in[28];
    const float* ln_x_b  = (const float*)d_in[29];
    const float* ln1_w   = (const float*)d_in[30];
    const float* ln1_b   = (const float*)d_in[31];

    float* sc = nullptr;
    cudaGetSymbolAddress((void**)&sc, d_scratch);

    float* p_xn = sc + OFS_XN;
    float* p_xr = sc + OFS_XR;
    float* p_xw = sc + OFS_XW;
    float* p_xk = sc + OFS_XK;
    float* p_xv = sc + OFS_XV;
    float* p_xa = sc + OFS_XA;
    float* p_xg = sc + OFS_XG;
    float* p_r  = sc + OFS_R;
    float* p_k  = sc + OFS_K;
    float* p_v  = sc + OFS_V;
    float* p_g  = sc + OFS_G;
    float* p_a  = sc + OFS_A;
    float* p_wd = sc + OFS_WD;
    float* p_vm = sc + OFS_VM;
    float* p_kf = sc + OFS_KF;
    float* p_vf = sc + OFS_VF;
    float* p_as = sc + OFS_AS;
    float* p_bs = sc + OFS_BS;
    float* p_y  = sc + OFS_Y;
    float* p_op = sc + OFS_OP;
    float* p_gt = sc + OFS_GT;
    float* p_at = sc + OFS_AT;
    float* p_wt = sc + OFS_WT;
    float* p_vt = sc + OFS_VT;

    // Output tuple layout: [main T*H | state1_out H | state2_out NH*HS*HS | v_first T*H]
    float* out = (float*)d_out;
    const size_t nMain = TH;
    const size_t nS1   = H_DIM;
    const size_t nS2   = (size_t)NHEAD * HSZ * HSZ;
    float* o_s1 = ((size_t)out_size >= nMain + nS1)             ? out + nMain              : nullptr;
    float* o_s2 = ((size_t)out_size >= nMain + nS1 + nS2)       ? out + nMain + nS1        : nullptr;
    float* o_vf = ((size_t)out_size >= nMain + nS1 + nS2 + TH)  ? out + nMain + nS1 + nS2  : nullptr;

    // 1. LayerNorm + state1_out
    ln1_kernel<<<T_LEN, 256>>>(x, ln1_w, ln1_b, p_xn, o_s1);

    // 2. Token-shift mixing
    mix_kernel<<<4096, 512>>>(p_xn, state1, x_r, x_w, x_k, x_v, x_a, x_g,
                              p_xr, p_xw, p_xk, p_xv, p_xa, p_xg);

    // 3. Big projections (NT)
    dim3 gbig(32, 16);
    gemm_kernel<<<gbig, 256>>>(p_xr, W_r, p_r, T_LEN, H_DIM, H_DIM, 1, 0, nullptr, nullptr);
    gemm_kernel<<<gbig, 256>>>(p_xk, W_k, p_k, T_LEN, H_DIM, H_DIM, 1, 0, nullptr, nullptr);
    gemm_kernel<<<gbig, 256>>>(p_xv, W_v, p_v, T_LEN, H_DIM, H_DIM, 1, 0, nullptr, nullptr);

    // 4. Small MLP stage 1 (NN)
    gemm_kernel<<<dim3(2, 16), 256>>>(p_xg, g1, p_gt, T_LEN, 128, H_DIM, 0, 1, nullptr, nullptr);
    gemm_kernel<<<dim3(1, 16), 256>>>(p_xa, a1, p_at, T_LEN, 64,  H_DIM, 0, 0, nullptr, nullptr);
    gemm_kernel<<<dim3(1, 16), 256>>>(p_xw, w1, p_wt, T_LEN, 64,  H_DIM, 0, 2, nullptr, nullptr);
    gemm_kernel<<<dim3(1, 16), 256>>>(p_xv, v1, p_vt, T_LEN, 32,  H_DIM, 0, 0, nullptr, nullptr);

    // 5. Small MLP stage 2 (NN) with fused epilogues
    gemm_kernel<<<gbig, 256>>>(p_gt, g2, p_g,  T_LEN, H_DIM, 128, 0, 0, nullptr, nullptr);
    gemm_kernel<<<gbig, 256>>>(p_at, a2, p_a,  T_LEN, H_DIM, 64,  0, 3, a0, nullptr);
    gemm_kernel<<<gbig, 256>>>(p_wt, w2, p_wd, T_LEN, H_DIM, 64,  0, 4, w0, nullptr);
    gemm_kernel<<<gbig, 256>>>(p_vt, v2, p_vm, T_LEN, H_DIM, 32,  0, 3, v0, nullptr);

    // 6. Per-(t,head) preprocessing
    prep_kernel<<<T_LEN * NHEAD, 64>>>(p_k, p_a, p_v, p_vm, v_first, k_k, k_a,
                                       p_kf, p_vf, p_as, p_bs);

    // 7. Sequential scan + state2_out
    scan_kernel<<<NHEAD, 128>>>(p_r, p_wd, p_kf, p_as, p_bs, p_vf, state2, p_y, o_s2);

    // 8. GroupNorm + bonus + gate
    post_kernel<<<T_LEN * NHEAD, 64>>>(p_y, p_r, p_kf, p_vf, p_g, r_k, ln_x_w, ln_x_b, p_op);

    // 9. Output projection with residual add (NT, mode 5)
    gemm_kernel<<<gbig, 256>>>(p_op, W_o, out, T_LEN, H_DIM, H_DIM, 1, 5, nullptr, x);

    // 10. v_first passthrough
    if (o_vf != nullptr) {
        copy_kernel<<<4096, 512>>>(v_first, o_vf, TH);
    }
}